// round 12
// baseline (speedup 1.0000x reference)
#include <cuda_runtime.h>
#include <cuda_bf16.h>
#include <math.h>
#include <stdint.h>

// ---- problem constants ----
#define BB    128
#define TU    256
#define TB    128
#define TP    64
#define HD    512
#define VD    3000
#define VOOVD 3400
#define PTRD  32
#define XDP   2112   // padded GRU input width (2080 -> 2112)
#define G3    1536
#define NEGV  (-1e20f)

// ---- scratch (device globals; no allocation allowed) ----
__device__ float g_p[BB * HD];
__device__ float g_score_u[BB * TU];
__device__ float g_score_b[BB * TB];
__device__ float g_score_p[BB * TP];
__device__ float g_ctx_u[BB * HD];
__device__ float g_ctx_b[BB * HD];
__device__ float g_ctx_p[BB * HD];
__device__ float g_gi[BB * G3];
__device__ float g_gi2[BB * G3];
__device__ float g_gh[BB * G3];
__device__ float g_hnew[BB * HD];
__device__ float g_gen[BB * VD];
__device__ float g_cpraw[BB * TB];
__device__ float g_zerob[G3];          // zero bias (static zero-init)

// bf16 staged operands
// g_wsc is FRAG-MAJOR: [mat][ni(2)][kc(8)][tn(32)][tk(4)][lane(32)][8B]
__device__ __nv_bfloat16 g_wsc[2][512 * 512];
__device__ __nv_bfloat16 g_w1b[512 * 512];        // attn_W1 (row-major n,k)
__device__ __nv_bfloat16 g_wihb[G3 * XDP];        // gru_W_ih padded K
__device__ __nv_bfloat16 g_whhb[G3 * 512];
__device__ __nv_bfloat16 g_wgenb[3008 * 512];     // padded N rows
__device__ __nv_bfloat16 g_h0b[BB * 512];
__device__ __nv_bfloat16 g_xb[BB * XDP];
__device__ __nv_bfloat16 g_hnb[BB * 512];

// =====================================================================
// helpers (sm_80+ PTX; compiles at plain compute_103)
// =====================================================================
__device__ __forceinline__ void mma_bf16(float* d,
    uint32_t a0, uint32_t a1, uint32_t a2, uint32_t a3,
    uint32_t b0, uint32_t b1)
{
    asm volatile(
        "mma.sync.aligned.m16n8k16.row.col.f32.bf16.bf16.f32 "
        "{%0,%1,%2,%3}, {%4,%5,%6,%7}, {%8,%9}, {%0,%1,%2,%3};"
        : "+f"(d[0]), "+f"(d[1]), "+f"(d[2]), "+f"(d[3])
        : "r"(a0), "r"(a1), "r"(a2), "r"(a3), "r"(b0), "r"(b1));
}
__device__ __forceinline__ void cpa16(uint32_t s, const void* g) {
    asm volatile("cp.async.cg.shared.global [%0], [%1], 16;" :: "r"(s), "l"(g));
}
__device__ __forceinline__ void cpa_commit() {
    asm volatile("cp.async.commit_group;");
}
__device__ __forceinline__ void cpa_wait1() {
    asm volatile("cp.async.wait_group 1;");
}
__device__ __forceinline__ float tanh_fast(float x) {
    float y; asm("tanh.approx.f32 %0, %1;" : "=f"(y) : "f"(x)); return y;
}
__device__ __forceinline__ uint32_t pack_bf16(float a, float b) {
    __nv_bfloat162 t = __floats2bfloat162_rn(a, b);
    return *(uint32_t*)&t;
}

// frag-major address for score weights (within one 512x512 matrix), bytes
__device__ __forceinline__ size_t wfrag_off(int n, int k) {
    int ni = n >> 8, nin = n & 255, tn = nin >> 3, grB = nin & 7;
    int kc = k >> 6, tk = (k >> 4) & 3, kin = k & 15;
    int slot = kin >> 3, tg = (kin & 7) >> 1, e = kin & 1;
    return (((size_t)(ni * 8 + kc) * 128 + tn * 4 + tk) * 32 + grB * 4 + tg) * 8
           + slot * 4 + e * 2;
}

// =====================================================================
// Stage everything to bf16 once.
// =====================================================================
#define SO1 262144
#define SO2 524288
#define SO3 786432
#define SO4 4030464   // +1536*2112
#define SO5 4816896   // +1536*512
#define SO6 6356992   // +3008*512
#define SO7 6422528   // +128*512
__global__ void stage_all_kernel(
    const float* __restrict__ attn_W, const float* __restrict__ Wcopy_w,
    const float* __restrict__ W_ih, const float* __restrict__ W_hh,
    const float* __restrict__ Wgen_w, const float* __restrict__ h0)
{
    int idx = blockIdx.x * blockDim.x + threadIdx.x;
    if (idx >= SO7) return;
    if (idx < SO1) {
        int n = idx >> 9, k = idx & 511;
        g_w1b[idx] = __float2bfloat16(attn_W[n * 1024 + k]);
    } else if (idx < SO2) {
        int r = idx - SO1; int n = r >> 9, k = r & 511;
        *(__nv_bfloat16*)((char*)g_wsc[0] + wfrag_off(n, k)) =
            __float2bfloat16(attn_W[n * 1024 + 512 + k]);
    } else if (idx < SO3) {
        int r = idx - SO2; int n = r >> 9, k = r & 511;
        *(__nv_bfloat16*)((char*)g_wsc[1] + wfrag_off(n, k)) =
            __float2bfloat16(Wcopy_w[r]);
    } else if (idx < SO4) {
        int r = idx - SO3; int n = r / XDP, k = r % XDP;
        g_wihb[r] = (k < 2080) ? __float2bfloat16(W_ih[(size_t)n * 2080 + k])
                               : __float2bfloat16(0.f);
    } else if (idx < SO5) {
        int r = idx - SO4;
        g_whhb[r] = __float2bfloat16(W_hh[r]);
    } else if (idx < SO6) {
        int r = idx - SO5; int n = r >> 9;
        g_wgenb[r] = (n < VD) ? __float2bfloat16(Wgen_w[r]) : __float2bfloat16(0.f);
    } else {
        int r = idx - SO6;
        g_h0b[r] = __float2bfloat16(h0[r]);
    }
}

// =====================================================================
// Generic bf16 MMA GEMM body (row-major staged weights; koff for split-K)
// =====================================================================
#define GM_STR 36
#define GM_BUF 18432
#define GM_SMEM (4 * GM_BUF)

__device__ __forceinline__ void gm_prefetch(
    const __nv_bfloat16* __restrict__ A, const __nv_bfloat16* __restrict__ W,
    int nbase, int kc, int K, int bb, uint32_t smb, int tid)
{
    const __nv_bfloat16* asrc = A + kc * 64;
    uint32_t ad = smb + bb * GM_BUF;
    #pragma unroll
    for (int it = 0; it < 4; it++) {
        int idx = tid + it * 256;
        int row = idx >> 3, ch = idx & 7;
        cpa16(ad + row * 144 + ch * 16, asrc + (size_t)row * K + ch * 8);
    }
    const __nv_bfloat16* bsrc = W + (size_t)nbase * K + kc * 64;
    uint32_t bd = smb + 2 * GM_BUF + bb * GM_BUF;
    #pragma unroll
    for (int it = 0; it < 4; it++) {
        int idx = tid + it * 256;
        int row = idx >> 3, ch = idx & 7;
        cpa16(bd + row * 144 + ch * 16, bsrc + (size_t)row * K + ch * 8);
    }
    cpa_commit();
}

__device__ __forceinline__ void gemm_mma_body(
    const __nv_bfloat16* __restrict__ A, const __nv_bfloat16* __restrict__ W,
    const float* __restrict__ bias, float* __restrict__ C,
    int ldc, int nbase, int K, int Nlim, int koff, int nk)
{
    extern __shared__ char smc[];
    uint32_t smb = (uint32_t)__cvta_generic_to_shared(smc);
    int tid = threadIdx.x;
    int wid = tid >> 5, lane = tid & 31;
    int gr = lane >> 2, tg = lane & 3;
    int m0 = (wid & 1) * 64;
    int n0 = (wid >> 1) * 32;

    const __nv_bfloat16* Ao = A + koff;
    const __nv_bfloat16* Wo = W + koff;

    gm_prefetch(Ao, Wo, nbase, 0, K, 0, smb, tid);
    gm_prefetch(Ao, Wo, nbase, 1, K, 1, smb, tid);

    float acc[4][4][4];
    #pragma unroll
    for (int mt = 0; mt < 4; mt++)
        #pragma unroll
        for (int nt = 0; nt < 4; nt++)
            #pragma unroll
            for (int q = 0; q < 4; q++) acc[mt][nt][q] = 0.f;

    for (int kc = 0; kc < nk; kc++) {
        int bb = kc & 1;
        cpa_wait1();
        __syncthreads();
        const uint32_t* Au = (const uint32_t*)(smc + bb * GM_BUF);
        const uint32_t* Bu = (const uint32_t*)(smc + 2 * GM_BUF + bb * GM_BUF);
        #pragma unroll
        for (int kk = 0; kk < 4; kk++) {
            int kw = kk * 8 + tg;
            uint32_t bf[4][2];
            #pragma unroll
            for (int nt = 0; nt < 4; nt++) {
                int bn = n0 + nt * 8 + gr;
                bf[nt][0] = Bu[bn * GM_STR + kw];
                bf[nt][1] = Bu[bn * GM_STR + kw + 4];
            }
            #pragma unroll
            for (int mt = 0; mt < 4; mt++) {
                int ar = m0 + mt * 16 + gr;
                uint32_t a0 = Au[ar * GM_STR + kw];
                uint32_t a1 = Au[(ar + 8) * GM_STR + kw];
                uint32_t a2 = Au[ar * GM_STR + kw + 4];
                uint32_t a3 = Au[(ar + 8) * GM_STR + kw + 4];
                #pragma unroll
                for (int nt = 0; nt < 4; nt++)
                    mma_bf16(acc[mt][nt], a0, a1, a2, a3, bf[nt][0], bf[nt][1]);
            }
        }
        __syncthreads();
        if (kc + 2 < nk)
            gm_prefetch(Ao, Wo, nbase, kc + 2, K, bb, smb, tid);
        else
            cpa_commit();
    }

    #pragma unroll
    for (int mt = 0; mt < 4; mt++) {
        int m = m0 + mt * 16 + gr;
        #pragma unroll
        for (int nt = 0; nt < 4; nt++) {
            int n = nbase + n0 + nt * 8 + tg * 2;
            if (n < Nlim) {
                float b0 = bias[n], b1 = bias[n + 1];
                *(float2*)(C + (size_t)m * ldc + n) =
                    make_float2(acc[mt][nt][0] + b0, acc[mt][nt][1] + b1);
                *(float2*)(C + (size_t)(m + 8) * ldc + n) =
                    make_float2(acc[mt][nt][2] + b0, acc[mt][nt][3] + b1);
            }
        }
    }
}

__global__ __launch_bounds__(256, 1) void mma_p_kernel(const float* __restrict__ attn_b)
{
    gemm_mma_body(g_h0b, g_w1b, attn_b, g_p, 512, blockIdx.x * 128, 512, 512, 0, 8);
}
// split-K GRU: [0,12) gi K-chunks 0..16; [12,24) gi chunks 17..32 -> g_gi2;
// [24,36) gh
__global__ __launch_bounds__(256, 1) void mma_gru_kernel(
    const float* __restrict__ b_ih, const float* __restrict__ b_hh)
{
    int bx = blockIdx.x;
    if (bx < 12)
        gemm_mma_body(g_xb, g_wihb, b_ih, g_gi, G3, bx * 128, XDP, G3, 0, 17);
    else if (bx < 24)
        gemm_mma_body(g_xb, g_wihb, g_zerob, g_gi2, G3, (bx - 12) * 128, XDP, G3,
                      17 * 64, 16);
    else
        gemm_mma_body(g_h0b, g_whhb, b_hh, g_gh, G3, (bx - 24) * 128, 512, G3, 0, 8);
}

// =====================================================================
// bf16 tensor-core score body, FRAG-MAJOR smem:
//   score[bm+m] = sum_n vvec[b,n] * tanh(addv[b,n] + sum_k Enc[m,k]*W[n,k])
// A resident: [kc(8)][tm(8)][tk(4)][lane(32)][16B]  (LDS.128 per frag)
// B streamed:  [tn(32)][tk(4)][lane(32)][8B] per 64-k chunk (LDS.64 per frag)
// =====================================================================
#define A_OFF   0
#define B_OFF   131072
#define B_BUF_B 32768
#define SP_OFF  196608
#define SV_OFF  200704
#define RED_OFF 204800
#define SMEM_SZ 213504

__device__ __forceinline__ void b_prefetch(
    const __nv_bfloat16* __restrict__ Wb, int ni, int kc, int bb,
    uint32_t smb, int tid)
{
    const char* src = (const char*)Wb + (size_t)(ni * 8 + kc) * 32768;
    uint32_t dst = smb + B_OFF + bb * B_BUF_B;
    #pragma unroll
    for (int it = 0; it < 8; it++) {
        int o = (tid + it * 256) << 4;
        cpa16(dst + o, src + o);
    }
    cpa_commit();
}

__device__ __forceinline__ void score_body(
    const float* __restrict__ Enc,
    const __nv_bfloat16* __restrict__ Wb,
    const float* __restrict__ addv, int a_stride,
    const float* __restrict__ vvec, int v_stride,
    float* __restrict__ score, int T, int bm)
{
    extern __shared__ char smc[];
    uint32_t smb = (uint32_t)__cvta_generic_to_shared(smc);
    float* smf = (float*)smc;
    int tid = threadIdx.x;
    int wid = tid >> 5, lane = tid & 31;
    int gr = lane >> 2, tg = lane & 3;
    int bA = bm / T;

    int m0 = (wid & 1) * 64;
    int n0 = (wid >> 1) * 64;

    b_prefetch(Wb, 0, 0, 0, smb, tid);
    b_prefetch(Wb, 0, 1, 1, smb, tid);

    for (int i = tid; i < 1024; i += 256) {
        int sl = i >> 9, n = i & 511;
        int bs = (bm + sl * 64) / T;
        smf[(SP_OFF >> 2) + i] = addv[(size_t)bs * a_stride + n];
        smf[(SV_OFF >> 2) + i] = vvec[(size_t)bs * v_stride + n];
    }

    // A fill: f32 -> bf16, frag-major
    for (int it = 0; it < 64; it++) {
        int idx = tid + it * 256;               // 0..16383
        int row = idx >> 7, c4 = idx & 127;
        int k = c4 << 2;
        float4 v = *(const float4*)(Enc + (size_t)(bm + row) * 512 + k);
        uint32_t w0 = pack_bf16(v.x, v.y);
        uint32_t w1 = pack_bf16(v.z, v.w);
        int kcA = k >> 6, tk = (k >> 4) & 3;
        int kin = k & 15;                       // 0,4,8,12
        int tgA = (kin & 7) >> 1;               // 0 or 2
        int slot_hi = kin >> 3;
        int tm = row >> 4, rr = row & 15;
        int grA = rr & 7, hi = rr >> 3;
        int aidx = hi + slot_hi * 2;
        uint32_t base = A_OFF
            + ((uint32_t)(kcA * 1024 + tm * 128 + tk * 32 + grA * 4 + tgA) << 4)
            + (aidx << 2);
        *(uint32_t*)(smc + base) = w0;
        *(uint32_t*)(smc + base + 16) = w1;
    }
    __syncthreads();

    float acc[4][8][4];

    for (int ph = 0; ph < 16; ph++) {
        int ni = ph >> 3, kc = ph & 7, bb = ph & 1;
        if (kc == 0) {
            #pragma unroll
            for (int mt = 0; mt < 4; mt++)
                #pragma unroll
                for (int nt = 0; nt < 8; nt++)
                    #pragma unroll
                    for (int q = 0; q < 4; q++) acc[mt][nt][q] = 0.f;
        }
        cpa_wait1();
        __syncthreads();

        const char* Bb = smc + B_OFF + bb * B_BUF_B;
        #pragma unroll
        for (int kk = 0; kk < 4; kk++) {
            uint2 bf[8];
            #pragma unroll
            for (int nt = 0; nt < 8; nt++) {
                int btile = ((n0 >> 3) + nt) * 4 + kk;
                bf[nt] = *(const uint2*)(Bb + ((btile * 32 + lane) << 3));
            }
            #pragma unroll
            for (int mt = 0; mt < 4; mt++) {
                int atile = kc * 1024 + ((m0 >> 4) + mt) * 128 + kk * 32 + lane;
                uint4 av = *(const uint4*)(smc + A_OFF + ((uint32_t)atile << 4));
                #pragma unroll
                for (int nt = 0; nt < 8; nt++)
                    mma_bf16(acc[mt][nt], av.x, av.y, av.z, av.w,
                             bf[nt].x, bf[nt].y);
            }
        }
        __syncthreads();

        int ph2 = ph + 2;
        if (ph2 < 16)
            b_prefetch(Wb, ph2 >> 3, ph2 & 7, bb, smb, tid);
        else
            cpa_commit();

        if (kc == 7) {
            int slot = tg + 4 * (wid >> 1);
            int soff = ((bm + m0) / T - bA) * 512;
            const float* sp = smf + (SP_OFF >> 2) + soff;
            const float* sv = smf + (SV_OFF >> 2) + soff;
            float* red = smf + (RED_OFF >> 2);
            #pragma unroll
            for (int mt = 0; mt < 4; mt++) {
                int row = m0 + mt * 16 + gr;
                float p0 = 0.f, p1 = 0.f;
                #pragma unroll
                for (int nt = 0; nt < 8; nt++) {
                    int n = ni * 256 + n0 + nt * 8 + tg * 2;
                    float sp0 = sp[n], sp1 = sp[n + 1];
                    float sv0 = sv[n], sv1 = sv[n + 1];
                    p0 = fmaf(tanh_fast(sp0 + acc[mt][nt][0]), sv0, p0);
                    p0 = fmaf(tanh_fast(sp1 + acc[mt][nt][1]), sv1, p0);
                    p1 = fmaf(tanh_fast(sp0 + acc[mt][nt][2]), sv0, p1);
                    p1 = fmaf(tanh_fast(sp1 + acc[mt][nt][3]), sv1, p1);
                }
                if (ni == 0) {
                    red[row * 17 + slot] = p0;
                    red[(row + 8) * 17 + slot] = p1;
                } else {
                    red[row * 17 + slot] += p0;
                    red[(row + 8) * 17 + slot] += p1;
                }
            }
        }
    }
    __syncthreads();
    if (tid < 128) {
        float* red = smf + (RED_OFF >> 2);
        float s = 0.f;
        #pragma unroll
        for (int j = 0; j < 16; j++) s += red[tid * 17 + j];
        score[bm + tid] = s;
    }
}

__global__ __launch_bounds__(256, 1) void score_attn_kernel(
    const float* __restrict__ usdx, const float* __restrict__ bspn,
    const float* __restrict__ pv, const float* __restrict__ vw)
{
    int bx = blockIdx.x;
    const float* enc; float* out; int T, bm;
    if (bx < 256)      { enc = usdx; out = g_score_u; T = TU; bm = bx * 128; }
    else if (bx < 384) { enc = bspn; out = g_score_b; T = TB; bm = (bx - 256) * 128; }
    else               { enc = pv;   out = g_score_p; T = TP; bm = (bx - 384) * 128; }
    score_body(enc, g_wsc[0], g_p, 512, vw, 0, out, T, bm);
}

// fused tail: cp scores (128 blocks) + gen logits GEMM (24 blocks)
__global__ __launch_bounds__(256, 1) void tail_kernel(
    const float* __restrict__ Wgen_b, const float* __restrict__ wcb,
    const float* __restrict__ bspn)
{
    int bx = blockIdx.x;
    if (bx < 128)
        score_body(bspn, g_wsc[1], wcb, 0, g_hnew, 512, g_cpraw, TB, bx * 128);
    else
        gemm_mma_body(g_hnb, g_wgenb, Wgen_b, g_gen, VD, (bx - 128) * 128, 512, VD,
                      0, 8);
}

// =====================================================================
// Context with fused softmax: ctx[b,h] = softmax(mask(score))[t] . enc
// grid = 1536 (3 segs x 128 b x 4 h-chunks), 128 threads. 8-way unroll.
// =====================================================================
__global__ __launch_bounds__(128) void ctx_kernel(
    const float* __restrict__ usdx, const float* __restrict__ bspn,
    const float* __restrict__ pv,
    const int* __restrict__ usdx_ids, const int* __restrict__ bspn_ids,
    const int* __restrict__ pv_ids)
{
    int bx = blockIdx.x;
    const float* sc; const float* enc; const int* ids; float* ctx; int T, r;
    if (bx < 512)       { sc = g_score_u; enc = usdx; ids = usdx_ids; ctx = g_ctx_u; T = TU; r = bx; }
    else if (bx < 1024) { sc = g_score_b; enc = bspn; ids = bspn_ids; ctx = g_ctx_b; T = TB; r = bx - 512; }
    else                { sc = g_score_p; enc = pv;   ids = pv_ids;   ctx = g_ctx_p; T = TP; r = bx - 1024; }
    int b = r >> 2, hc = r & 3;
    int tid = threadIdx.x;

    __shared__ float sa[256];
    __shared__ float rb[128];

    float lmx = -INFINITY;
    for (int i = tid; i < T; i += 128) {
        float s = sc[b * T + i];
        if (ids[b * T + i] == 0) s = NEGV;
        sa[i] = s;
        lmx = fmaxf(lmx, s);
    }
    rb[tid] = lmx;
    __syncthreads();
    for (int s = 64; s > 0; s >>= 1) {
        if (tid < s) rb[tid] = fmaxf(rb[tid], rb[tid + s]);
        __syncthreads();
    }
    float mx = rb[0];
    __syncthreads();
    float lsum = 0.f;
    for (int i = tid; i < T; i += 128) {
        float e = expf(sa[i] - mx);
        sa[i] = e;
        lsum += e;
    }
    rb[tid] = lsum;
    __syncthreads();
    for (int s = 64; s > 0; s >>= 1) {
        if (tid < s) rb[tid] += rb[tid + s];
        __syncthreads();
    }
    float inv = 1.0f / rb[0];
    __syncthreads();

    const float* ep = enc + (size_t)b * T * 512 + hc * 128 + tid;
    float a0 = 0.f, a1 = 0.f, a2 = 0.f, a3 = 0.f;
    float a4 = 0.f, a5 = 0.f, a6 = 0.f, a7 = 0.f;
    for (int t = 0; t < T; t += 8) {
        a0 = fmaf(sa[t],     ep[(size_t)t * 512],       a0);
        a1 = fmaf(sa[t + 1], ep[(size_t)(t + 1) * 512], a1);
        a2 = fmaf(sa[t + 2], ep[(size_t)(t + 2) * 512], a2);
        a3 = fmaf(sa[t + 3], ep[(size_t)(t + 3) * 512], a3);
        a4 = fmaf(sa[t + 4], ep[(size_t)(t + 4) * 512], a4);
        a5 = fmaf(sa[t + 5], ep[(size_t)(t + 5) * 512], a5);
        a6 = fmaf(sa[t + 6], ep[(size_t)(t + 6) * 512], a6);
        a7 = fmaf(sa[t + 7], ep[(size_t)(t + 7) * 512], a7);
    }
    ctx[b * 512 + hc * 128 + tid] =
        (((a0 + a1) + (a2 + a3)) + ((a4 + a5) + (a6 + a7))) * inv;
}

// =====================================================================
// Assemble GRU input directly in bf16
// =====================================================================
__global__ void assemble_x_kernel(
    const int* __restrict__ w, const float* __restrict__ emb_table,
    const float* __restrict__ db)
{
    int idx = blockIdx.x * blockDim.x + threadIdx.x;
    if (idx >= BB * XDP) return;
    int b = idx / XDP, c = idx % XDP;
    float v;
    if (c < 512)       v = emb_table[(size_t)w[b] * 512 + c];
    else if (c < 1024) v = g_ctx_u[b * HD + c - 512];
    else if (c < 1536) v = g_ctx_b[b * HD + c - 1024];
    else if (c < 2048) v = g_ctx_p[b * HD + c - 1536];
    else if (c < 2080) v = db[b * PTRD + (c - 2048)];
    else               v = 0.f;
    g_xb[idx] = __float2bfloat16(v);
}

// =====================================================================
// GRU gate combine (sums split-K gi halves); writes hnew f32 + bf16.
// =====================================================================
__global__ void gru_gate_kernel(const float* __restrict__ h0)
{
    int idx = blockIdx.x * blockDim.x + threadIdx.x;
    if (idx >= BB * HD) return;
    int b = idx / HD, i = idx % HD;
    const float* gi = g_gi + (size_t)b * G3;
    const float* gi2 = g_gi2 + (size_t)b * G3;
    const float* gh = g_gh + (size_t)b * G3;
    float gr_ = gi[i] + gi2[i] + gh[i];
    float gz = gi[512 + i] + gi2[512 + i] + gh[512 + i];
    float r = 1.f / (1.f + expf(-gr_));
    float z = 1.f / (1.f + expf(-gz));
    float n = tanhf(gi[1024 + i] + gi2[1024 + i] + r * gh[1024 + i]);
    float hv = (1.f - z) * n + z * h0[idx];
    g_hnew[idx] = hv;
    g_hnb[idx] = __float2bfloat16(hv);
}

// =====================================================================
// Final: scatter cps, log-softmax over [gen | cps], merge + OOV.
// =====================================================================
__global__ __launch_bounds__(256) void final_kernel(
    const int* __restrict__ bspn_ids, const int* __restrict__ nounk,
    float* __restrict__ out)
{
    int b = blockIdx.x;
    int tid = threadIdx.x;
    __shared__ float s_cps[VD + TB];
    __shared__ float s_cpm[TB];
    __shared__ int   s_nk[TB];
    __shared__ float rbuf[256];

    for (int i = tid; i < VD + TB; i += 256) s_cps[i] = 0.f;
    if (tid < TB) {
        float c = g_cpraw[b * TB + tid];
        if (bspn_ids[b * TB + tid] == 0) c = NEGV;
        s_cpm[tid] = c;
        s_nk[tid] = nounk[b * TB + tid];
    }
    __syncthreads();
    if (tid == 0) {
        for (int j = 0; j < TB; j++) {
            int nk = s_nk[j];
            float c = s_cpm[j];
            if (nk < VD) s_cps[nk] += c;
            else         s_cps[VD + j] = c;
        }
    }
    __syncthreads();

    const float* genb = g_gen + (size_t)b * VD;
    float mx = -INFINITY;
    for (int i = tid; i < VD; i += 256) mx = fmaxf(mx, genb[i]);
    for (int i = tid; i < VD + TB; i += 256) mx = fmaxf(mx, s_cps[i]);
    rbuf[tid] = mx;
    __syncthreads();
    for (int s = 128; s > 0; s >>= 1) {
        if (tid < s) rbuf[tid] = fmaxf(rbuf[tid], rbuf[tid + s]);
        __syncthreads();
    }
    mx = rbuf[0];
    __syncthreads();
    float sm = 0.f;
    for (int i = tid; i < VD; i += 256) sm += expf(genb[i] - mx);
    for (int i = tid; i < VD + TB; i += 256) sm += expf(s_cps[i] - mx);
    rbuf[tid] = sm;
    __syncthreads();
    for (int s = 128; s > 0; s >>= 1) {
        if (tid < s) rbuf[tid] += rbuf[tid + s];
        __syncthreads();
    }
    float lse = mx + logf(rbuf[0]);
    __syncthreads();

    float* outb = out + (size_t)b * VOOVD;
    for (int n = tid; n < VD; n += 256) {
        float a = genb[n], c = s_cps[n];
        float m2 = fmaxf(a, c);
        outb[n] = m2 + logf(expf(a - m2) + expf(c - m2)) - lse;
    }
    for (int k = tid; k < VOOVD - VD; k += 256) {
        float add = 0.f;
        int target = VD + k;
        for (int j = 0; j < TB; j++)
            if (s_nk[j] == target) add += expf(s_cpm[j] - lse);
        outb[VD + k] = (add > 0.f) ? logf(add) : NEGV;
    }
}

// =====================================================================
// Host launcher
// =====================================================================
extern "C" void kernel_launch(void* const* d_in, const int* in_sizes, int n_in,
                              void* d_out, int out_size)
{
    const int*   dec_last_w = (const int*)  d_in[0];
    const float* h0         = (const float*)d_in[1];
    const float* usdx_h     = (const float*)d_in[2];
    const float* bspn_h     = (const float*)d_in[3];
    const float* pvaspn_h   = (const float*)d_in[4];
    const float* db         = (const float*)d_in[5];
    const int*   usdx_ids   = (const int*)  d_in[6];
    const int*   bspn_ids   = (const int*)  d_in[7];
    const int*   pvaspn_ids = (const int*)  d_in[8];
    const int*   bspn_nounk = (const int*)  d_in[9];
    const float* emb_table  = (const float*)d_in[11];
    const float* attn_W     = (const float*)d_in[12];
    const float* attn_b     = (const float*)d_in[13];
    const float* v_w        = (const float*)d_in[14];
    const float* Wcopy_w    = (const float*)d_in[15];
    const float* Wcopy_b    = (const float*)d_in[16];
    const float* Wgen_w     = (const float*)d_in[17];
    const float* Wgen_b     = (const float*)d_in[18];
    const float* gru_W_ih   = (const float*)d_in[19];
    const float* gru_W_hh   = (const float*)d_in[20];
    const float* gru_b_ih   = (const float*)d_in[21];
    const float* gru_b_hh   = (const float*)d_in[22];
    float* out = (float*)d_out;

    cudaFuncSetAttribute(score_attn_kernel,
                         cudaFuncAttributeMaxDynamicSharedMemorySize, SMEM_SZ);
    cudaFuncSetAttribute(tail_kernel,
                         cudaFuncAttributeMaxDynamicSharedMemorySize, SMEM_SZ);
    cudaFuncSetAttribute(mma_p_kernel,
                         cudaFuncAttributeMaxDynamicSharedMemorySize, GM_SMEM);
    cudaFuncSetAttribute(mma_gru_kernel,
                         cudaFuncAttributeMaxDynamicSharedMemorySize, GM_SMEM);

    // 0) stage all operands to bf16 (score weights frag-major)
    stage_all_kernel<<<(SO7 + 255) / 256, 256>>>(
        attn_W, Wcopy_w, gru_W_ih, gru_W_hh, Wgen_w, h0);

    // 1) p = h0 @ W1^T + attn_b  (bf16 mma)
    mma_p_kernel<<<4, 256, GM_SMEM>>>(attn_b);

    // 2) all three attention scores, one bf16 tensor-core launch
    score_attn_kernel<<<448, 256, SMEM_SZ>>>(usdx_h, bspn_h, pvaspn_h, v_w);

    // 3) softmax+context fused
    ctx_kernel<<<1536, 128>>>(usdx_h, bspn_h, pvaspn_h,
                              usdx_ids, bspn_ids, pvaspn_ids);

    // 4) GRU (split-K gi)
    assemble_x_kernel<<<(BB * XDP + 255) / 256, 256>>>(dec_last_w, emb_table, db);
    mma_gru_kernel<<<36, 256, GM_SMEM>>>(gru_b_ih, gru_b_hh);
    gru_gate_kernel<<<(BB * HD + 255) / 256, 256>>>(h0);

    // 5) cp scores + gen logits fused (both depend only on hnew)
    tail_kernel<<<152, 256, SMEM_SZ>>>(Wgen_b, Wcopy_b, bspn_h);

    // 6) final scatter + log-softmax + merge
    final_kernel<<<BB, 256>>>(bspn_ids, bspn_nounk, out);
}

// round 13
// speedup vs baseline: 1.3738x; 1.3738x over previous
#include <cuda_runtime.h>
#include <cuda_bf16.h>
#include <math.h>
#include <stdint.h>

// ---- problem constants ----
#define BB    128
#define TU    256
#define TB    128
#define TP    64
#define HD    512
#define VD    3000
#define VOOVD 3400
#define PTRD  32
#define XDP   2112   // padded GRU input width (2080 -> 2112)
#define G3    1536
#define NEGV  (-1e20f)

// ---- scratch (device globals; no allocation allowed) ----
__device__ float g_p[BB * HD];
__device__ float g_score_u[BB * TU];
__device__ float g_score_b[BB * TB];
__device__ float g_score_p[BB * TP];
__device__ float g_ctx_u[BB * HD];
__device__ float g_ctx_b[BB * HD];
__device__ float g_ctx_p[BB * HD];
__device__ float g_gi[BB * G3];
__device__ float g_gi2[BB * G3];
__device__ float g_gh[BB * G3];
__device__ float g_hnew[BB * HD];
__device__ float g_gen[BB * VD];
__device__ float g_cpraw[BB * TB];
__device__ float g_zerob[G3];          // zero bias (static zero-init)

// bf16 staged operands
__device__ __nv_bfloat16 g_wsc[2][512 * 512];     // [0]=attn_W2, [1]=Wcopy (score path)
__device__ __nv_bfloat16 g_w1b[512 * 512];        // attn_W1
__device__ __nv_bfloat16 g_wihb[G3 * XDP];        // gru_W_ih padded K
__device__ __nv_bfloat16 g_whhb[G3 * 512];
__device__ __nv_bfloat16 g_wgenb[3008 * 512];     // padded N rows (zeros >= 3000)
__device__ __nv_bfloat16 g_h0b[BB * 512];
__device__ __nv_bfloat16 g_xb[BB * XDP];
__device__ __nv_bfloat16 g_hnb[BB * 512];

// =====================================================================
// helpers (sm_80+ PTX; compiles at plain compute_103)
// =====================================================================
__device__ __forceinline__ void mma_bf16(float* d,
    uint32_t a0, uint32_t a1, uint32_t a2, uint32_t a3,
    uint32_t b0, uint32_t b1)
{
    asm volatile(
        "mma.sync.aligned.m16n8k16.row.col.f32.bf16.bf16.f32 "
        "{%0,%1,%2,%3}, {%4,%5,%6,%7}, {%8,%9}, {%0,%1,%2,%3};"
        : "+f"(d[0]), "+f"(d[1]), "+f"(d[2]), "+f"(d[3])
        : "r"(a0), "r"(a1), "r"(a2), "r"(a3), "r"(b0), "r"(b1));
}
__device__ __forceinline__ void cpa16(uint32_t s, const void* g) {
    asm volatile("cp.async.cg.shared.global [%0], [%1], 16;" :: "r"(s), "l"(g));
}
__device__ __forceinline__ void cpa_commit() {
    asm volatile("cp.async.commit_group;");
}
__device__ __forceinline__ void cpa_wait1() {
    asm volatile("cp.async.wait_group 1;");
}
__device__ __forceinline__ float tanh_fast(float x) {
    float y; asm("tanh.approx.f32 %0, %1;" : "=f"(y) : "f"(x)); return y;
}
__device__ __forceinline__ uint32_t pack_bf16(float a, float b) {
    __nv_bfloat162 t = __floats2bfloat162_rn(a, b);
    return *(uint32_t*)&t;
}

// =====================================================================
// Stage everything to bf16 once.
// =====================================================================
#define SO1 262144
#define SO2 524288
#define SO3 786432
#define SO4 4030464   // +1536*2112
#define SO5 4816896   // +1536*512
#define SO6 6356992   // +3008*512
#define SO7 6422528   // +128*512
__global__ void stage_all_kernel(
    const float* __restrict__ attn_W, const float* __restrict__ Wcopy_w,
    const float* __restrict__ W_ih, const float* __restrict__ W_hh,
    const float* __restrict__ Wgen_w, const float* __restrict__ h0)
{
    int idx = blockIdx.x * blockDim.x + threadIdx.x;
    if (idx >= SO7) return;
    if (idx < SO1) {
        int n = idx >> 9, k = idx & 511;
        g_w1b[idx] = __float2bfloat16(attn_W[n * 1024 + k]);
    } else if (idx < SO2) {
        int r = idx - SO1; int n = r >> 9, k = r & 511;
        g_wsc[0][r] = __float2bfloat16(attn_W[n * 1024 + 512 + k]);
    } else if (idx < SO3) {
        int r = idx - SO2;
        g_wsc[1][r] = __float2bfloat16(Wcopy_w[r]);
    } else if (idx < SO4) {
        int r = idx - SO3; int n = r / XDP, k = r % XDP;
        g_wihb[r] = (k < 2080) ? __float2bfloat16(W_ih[(size_t)n * 2080 + k])
                               : __float2bfloat16(0.f);
    } else if (idx < SO5) {
        int r = idx - SO4;
        g_whhb[r] = __float2bfloat16(W_hh[r]);
    } else if (idx < SO6) {
        int r = idx - SO5; int n = r >> 9;
        g_wgenb[r] = (n < VD) ? __float2bfloat16(Wgen_w[r]) : __float2bfloat16(0.f);
    } else {
        int r = idx - SO6;
        g_h0b[r] = __float2bfloat16(h0[r]);
    }
}

// =====================================================================
// Generic bf16 MMA GEMM body (koff/nk for split-K)
// =====================================================================
#define GM_STR 36
#define GM_BUF 18432
#define GM_SMEM (4 * GM_BUF)

__device__ __forceinline__ void gm_prefetch(
    const __nv_bfloat16* __restrict__ A, const __nv_bfloat16* __restrict__ W,
    int nbase, int kc, int K, int bb, uint32_t smb, int tid)
{
    const __nv_bfloat16* asrc = A + kc * 64;
    uint32_t ad = smb + bb * GM_BUF;
    #pragma unroll
    for (int it = 0; it < 4; it++) {
        int idx = tid + it * 256;
        int row = idx >> 3, ch = idx & 7;
        cpa16(ad + row * 144 + ch * 16, asrc + (size_t)row * K + ch * 8);
    }
    const __nv_bfloat16* bsrc = W + (size_t)nbase * K + kc * 64;
    uint32_t bd = smb + 2 * GM_BUF + bb * GM_BUF;
    #pragma unroll
    for (int it = 0; it < 4; it++) {
        int idx = tid + it * 256;
        int row = idx >> 3, ch = idx & 7;
        cpa16(bd + row * 144 + ch * 16, bsrc + (size_t)row * K + ch * 8);
    }
    cpa_commit();
}

__device__ __forceinline__ void gemm_mma_body(
    const __nv_bfloat16* __restrict__ A, const __nv_bfloat16* __restrict__ W,
    const float* __restrict__ bias, float* __restrict__ C,
    int ldc, int nbase, int K, int Nlim, int koff, int nk)
{
    extern __shared__ char smc[];
    uint32_t smb = (uint32_t)__cvta_generic_to_shared(smc);
    int tid = threadIdx.x;
    int wid = tid >> 5, lane = tid & 31;
    int gr = lane >> 2, tg = lane & 3;
    int m0 = (wid & 1) * 64;
    int n0 = (wid >> 1) * 32;

    const __nv_bfloat16* Ao = A + koff;
    const __nv_bfloat16* Wo = W + koff;

    gm_prefetch(Ao, Wo, nbase, 0, K, 0, smb, tid);
    gm_prefetch(Ao, Wo, nbase, 1, K, 1, smb, tid);

    float acc[4][4][4];
    #pragma unroll
    for (int mt = 0; mt < 4; mt++)
        #pragma unroll
        for (int nt = 0; nt < 4; nt++)
            #pragma unroll
            for (int q = 0; q < 4; q++) acc[mt][nt][q] = 0.f;

    for (int kc = 0; kc < nk; kc++) {
        int bb = kc & 1;
        cpa_wait1();
        __syncthreads();
        const uint32_t* Au = (const uint32_t*)(smc + bb * GM_BUF);
        const uint32_t* Bu = (const uint32_t*)(smc + 2 * GM_BUF + bb * GM_BUF);
        #pragma unroll
        for (int kk = 0; kk < 4; kk++) {
            int kw = kk * 8 + tg;
            uint32_t bf[4][2];
            #pragma unroll
            for (int nt = 0; nt < 4; nt++) {
                int bn = n0 + nt * 8 + gr;
                bf[nt][0] = Bu[bn * GM_STR + kw];
                bf[nt][1] = Bu[bn * GM_STR + kw + 4];
            }
            #pragma unroll
            for (int mt = 0; mt < 4; mt++) {
                int ar = m0 + mt * 16 + gr;
                uint32_t a0 = Au[ar * GM_STR + kw];
                uint32_t a1 = Au[(ar + 8) * GM_STR + kw];
                uint32_t a2 = Au[ar * GM_STR + kw + 4];
                uint32_t a3 = Au[(ar + 8) * GM_STR + kw + 4];
                #pragma unroll
                for (int nt = 0; nt < 4; nt++)
                    mma_bf16(acc[mt][nt], a0, a1, a2, a3, bf[nt][0], bf[nt][1]);
            }
        }
        __syncthreads();
        if (kc + 2 < nk)
            gm_prefetch(Ao, Wo, nbase, kc + 2, K, bb, smb, tid);
        else
            cpa_commit();
    }

    #pragma unroll
    for (int mt = 0; mt < 4; mt++) {
        int m = m0 + mt * 16 + gr;
        #pragma unroll
        for (int nt = 0; nt < 4; nt++) {
            int n = nbase + n0 + nt * 8 + tg * 2;
            if (n < Nlim) {
                float b0 = bias[n], b1 = bias[n + 1];
                *(float2*)(C + (size_t)m * ldc + n) =
                    make_float2(acc[mt][nt][0] + b0, acc[mt][nt][1] + b1);
                *(float2*)(C + (size_t)(m + 8) * ldc + n) =
                    make_float2(acc[mt][nt][2] + b0, acc[mt][nt][3] + b1);
            }
        }
    }
}

__global__ __launch_bounds__(256, 1) void mma_p_kernel(const float* __restrict__ attn_b)
{
    gemm_mma_body(g_h0b, g_w1b, attn_b, g_p, 512, blockIdx.x * 128, 512, 512, 0, 8);
}
// split-K GRU: [0,12) gi K-chunks 0..16; [12,24) gi chunks 17..32 -> g_gi2;
// [24,36) gh
__global__ __launch_bounds__(256, 1) void mma_gru_kernel(
    const float* __restrict__ b_ih, const float* __restrict__ b_hh)
{
    int bx = blockIdx.x;
    if (bx < 12)
        gemm_mma_body(g_xb, g_wihb, b_ih, g_gi, G3, bx * 128, XDP, G3, 0, 17);
    else if (bx < 24)
        gemm_mma_body(g_xb, g_wihb, g_zerob, g_gi2, G3, (bx - 12) * 128, XDP, G3,
                      17 * 64, 16);
    else
        gemm_mma_body(g_h0b, g_whhb, b_hh, g_gh, G3, (bx - 24) * 128, 512, G3, 0, 8);
}

// =====================================================================
// bf16 tensor-core score body (R8/R11-proven):
//   score[bm+m] = sum_n vvec[b,n] * tanh(addv[b,n] + sum_k Enc[m,k]*W[n,k])
// Block = 128 M-rows x full N=512 (two 256-wide passes).
// A (128x512) resident in smem bf16, converted once from f32.
// B streamed as 64-k bf16 chunks via cp.async double buffer from staged W.
// =====================================================================
#define A_OFF   0
#define B_OFF   133120
#define B_BUF_B 36864
#define SP_OFF  (B_OFF + 2 * B_BUF_B)
#define SV_OFF  (SP_OFF + 4096)
#define RED_OFF (SV_OFF + 4096)
#define SMEM_SZ 223744

__device__ __forceinline__ void b_prefetch(
    const __nv_bfloat16* __restrict__ Wb, int ni, int kc, int bb,
    uint32_t smb, int tid)
{
    const __nv_bfloat16* src = Wb + (size_t)(ni * 256) * 512 + kc * 64;
    uint32_t dst = smb + B_OFF + bb * B_BUF_B;
    #pragma unroll
    for (int it = 0; it < 8; it++) {
        int idx = tid + it * 256;
        int row = idx >> 3, ch = idx & 7;
        cpa16(dst + row * 144 + ch * 16, src + (size_t)row * 512 + ch * 8);
    }
    cpa_commit();
}

__device__ __forceinline__ void score_body(
    const float* __restrict__ Enc,
    const __nv_bfloat16* __restrict__ Wb,
    const float* __restrict__ addv, int a_stride,
    const float* __restrict__ vvec, int v_stride,
    float* __restrict__ score, int T, int bm)
{
    extern __shared__ char smc[];
    uint32_t smb = (uint32_t)__cvta_generic_to_shared(smc);
    float* smf = (float*)smc;
    int tid = threadIdx.x;
    int wid = tid >> 5, lane = tid & 31;
    int gr = lane >> 2, tg = lane & 3;
    int bA = bm / T;

    int m0 = (wid & 1) * 64;
    int n0 = (wid >> 1) * 64;

    b_prefetch(Wb, 0, 0, 0, smb, tid);
    b_prefetch(Wb, 0, 1, 1, smb, tid);

    for (int i = tid; i < 1024; i += 256) {
        int sl = i >> 9, n = i & 511;
        int bs = (bm + sl * 64) / T;
        smf[(SP_OFF >> 2) + i] = addv[(size_t)bs * a_stride + n];
        smf[(SV_OFF >> 2) + i] = vvec[(size_t)bs * v_stride + n];
    }

    for (int it = 0; it < 64; it++) {
        int idx = tid + it * 256;
        int row = idx >> 7, k = (idx & 127) << 2;
        float4 v = *(const float4*)(Enc + (size_t)(bm + row) * 512 + k);
        uint2 pk = make_uint2(pack_bf16(v.x, v.y), pack_bf16(v.z, v.w));
        *(uint2*)(smc + A_OFF + row * 1040 + k * 2) = pk;
    }
    __syncthreads();

    const uint32_t* Au = (const uint32_t*)(smc + A_OFF);
    float acc[4][8][4];

    for (int ph = 0; ph < 16; ph++) {
        int ni = ph >> 3, kc = ph & 7, bb = ph & 1;
        if (kc == 0) {
            #pragma unroll
            for (int mt = 0; mt < 4; mt++)
                #pragma unroll
                for (int nt = 0; nt < 8; nt++)
                    #pragma unroll
                    for (int q = 0; q < 4; q++) acc[mt][nt][q] = 0.f;
        }
        cpa_wait1();
        __syncthreads();

        const uint32_t* Bu = (const uint32_t*)(smc + B_OFF + bb * B_BUF_B);
        #pragma unroll
        for (int kk = 0; kk < 4; kk++) {
            int kw = kk * 8 + tg;
            uint32_t bf[8][2];
            #pragma unroll
            for (int nt = 0; nt < 8; nt++) {
                int bn = n0 + nt * 8 + gr;
                bf[nt][0] = Bu[bn * 36 + kw];
                bf[nt][1] = Bu[bn * 36 + kw + 4];
            }
            int aw = kc * 32 + kw;
            #pragma unroll
            for (int mt = 0; mt < 4; mt++) {
                int ar = m0 + mt * 16 + gr;
                uint32_t a0 = Au[ar * 260 + aw];
                uint32_t a1 = Au[(ar + 8) * 260 + aw];
                uint32_t a2 = Au[ar * 260 + aw + 4];
                uint32_t a3 = Au[(ar + 8) * 260 + aw + 4];
                #pragma unroll
                for (int nt = 0; nt < 8; nt++)
                    mma_bf16(acc[mt][nt], a0, a1, a2, a3, bf[nt][0], bf[nt][1]);
            }
        }
        __syncthreads();

        int ph2 = ph + 2;
        if (ph2 < 16)
            b_prefetch(Wb, ph2 >> 3, ph2 & 7, bb, smb, tid);
        else
            cpa_commit();

        if (kc == 7) {
            int slot = tg + 4 * (wid >> 1);
            int soff = ((bm + m0) / T - bA) * 512;
            const float* sp = smf + (SP_OFF >> 2) + soff;
            const float* sv = smf + (SV_OFF >> 2) + soff;
            float* red = smf + (RED_OFF >> 2);
            #pragma unroll
            for (int mt = 0; mt < 4; mt++) {
                int row = m0 + mt * 16 + gr;
                float p0 = 0.f, p1 = 0.f;
                #pragma unroll
                for (int nt = 0; nt < 8; nt++) {
                    int n = ni * 256 + n0 + nt * 8 + tg * 2;
                    float sp0 = sp[n], sp1 = sp[n + 1];
                    float sv0 = sv[n], sv1 = sv[n + 1];
                    p0 = fmaf(tanh_fast(sp0 + acc[mt][nt][0]), sv0, p0);
                    p0 = fmaf(tanh_fast(sp1 + acc[mt][nt][1]), sv1, p0);
                    p1 = fmaf(tanh_fast(sp0 + acc[mt][nt][2]), sv0, p1);
                    p1 = fmaf(tanh_fast(sp1 + acc[mt][nt][3]), sv1, p1);
                }
                if (ni == 0) {
                    red[row * 17 + slot] = p0;
                    red[(row + 8) * 17 + slot] = p1;
                } else {
                    red[row * 17 + slot] += p0;
                    red[(row + 8) * 17 + slot] += p1;
                }
            }
        }
    }
    __syncthreads();
    if (tid < 128) {
        float* red = smf + (RED_OFF >> 2);
        float s = 0.f;
        #pragma unroll
        for (int j = 0; j < 16; j++) s += red[tid * 17 + j];
        score[bm + tid] = s;
    }
}

__global__ __launch_bounds__(256, 1) void score_attn_kernel(
    const float* __restrict__ usdx, const float* __restrict__ bspn,
    const float* __restrict__ pv, const float* __restrict__ vw)
{
    int bx = blockIdx.x;
    const float* enc; float* out; int T, bm;
    if (bx < 256)      { enc = usdx; out = g_score_u; T = TU; bm = bx * 128; }
    else if (bx < 384) { enc = bspn; out = g_score_b; T = TB; bm = (bx - 256) * 128; }
    else               { enc = pv;   out = g_score_p; T = TP; bm = (bx - 384) * 128; }
    score_body(enc, g_wsc[0], g_p, 512, vw, 0, out, T, bm);
}

// fused tail: cp scores (128 blocks) + gen logits GEMM (24 blocks)
__global__ __launch_bounds__(256, 1) void tail_kernel(
    const float* __restrict__ Wgen_b, const float* __restrict__ wcb,
    const float* __restrict__ bspn)
{
    int bx = blockIdx.x;
    if (bx < 128)
        score_body(bspn, g_wsc[1], wcb, 0, g_hnew, 512, g_cpraw, TB, bx * 128);
    else
        gemm_mma_body(g_hnb, g_wgenb, Wgen_b, g_gen, VD, (bx - 128) * 128, 512, VD,
                      0, 8);
}

// =====================================================================
// Context with fused softmax: ctx[b,h] = softmax(mask(score))[t] . enc
// grid = 1536 (3 segs x 128 b x 4 h-chunks), 128 threads. 4-way unroll.
// =====================================================================
__global__ __launch_bounds__(128) void ctx_kernel(
    const float* __restrict__ usdx, const float* __restrict__ bspn,
    const float* __restrict__ pv,
    const int* __restrict__ usdx_ids, const int* __restrict__ bspn_ids,
    const int* __restrict__ pv_ids)
{
    int bx = blockIdx.x;
    const float* sc; const float* enc; const int* ids; float* ctx; int T, r;
    if (bx < 512)       { sc = g_score_u; enc = usdx; ids = usdx_ids; ctx = g_ctx_u; T = TU; r = bx; }
    else if (bx < 1024) { sc = g_score_b; enc = bspn; ids = bspn_ids; ctx = g_ctx_b; T = TB; r = bx - 512; }
    else                { sc = g_score_p; enc = pv;   ids = pv_ids;   ctx = g_ctx_p; T = TP; r = bx - 1024; }
    int b = r >> 2, hc = r & 3;
    int tid = threadIdx.x;

    __shared__ float sa[256];
    __shared__ float rb[128];

    float lmx = -INFINITY;
    for (int i = tid; i < T; i += 128) {
        float s = sc[b * T + i];
        if (ids[b * T + i] == 0) s = NEGV;
        sa[i] = s;
        lmx = fmaxf(lmx, s);
    }
    rb[tid] = lmx;
    __syncthreads();
    for (int s = 64; s > 0; s >>= 1) {
        if (tid < s) rb[tid] = fmaxf(rb[tid], rb[tid + s]);
        __syncthreads();
    }
    float mx = rb[0];
    __syncthreads();
    float lsum = 0.f;
    for (int i = tid; i < T; i += 128) {
        float e = expf(sa[i] - mx);
        sa[i] = e;
        lsum += e;
    }
    rb[tid] = lsum;
    __syncthreads();
    for (int s = 64; s > 0; s >>= 1) {
        if (tid < s) rb[tid] += rb[tid + s];
        __syncthreads();
    }
    float inv = 1.0f / rb[0];
    __syncthreads();

    const float* ep = enc + (size_t)b * T * 512 + hc * 128 + tid;
    float a0 = 0.f, a1 = 0.f, a2 = 0.f, a3 = 0.f;
    for (int t = 0; t < T; t += 4) {
        a0 = fmaf(sa[t],     ep[(size_t)t * 512],       a0);
        a1 = fmaf(sa[t + 1], ep[(size_t)(t + 1) * 512], a1);
        a2 = fmaf(sa[t + 2], ep[(size_t)(t + 2) * 512], a2);
        a3 = fmaf(sa[t + 3], ep[(size_t)(t + 3) * 512], a3);
    }
    ctx[b * 512 + hc * 128 + tid] = ((a0 + a1) + (a2 + a3)) * inv;
}

// =====================================================================
// Assemble GRU input directly in bf16
// =====================================================================
__global__ void assemble_x_kernel(
    const int* __restrict__ w, const float* __restrict__ emb_table,
    const float* __restrict__ db)
{
    int idx = blockIdx.x * blockDim.x + threadIdx.x;
    if (idx >= BB * XDP) return;
    int b = idx / XDP, c = idx % XDP;
    float v;
    if (c < 512)       v = emb_table[(size_t)w[b] * 512 + c];
    else if (c < 1024) v = g_ctx_u[b * HD + c - 512];
    else if (c < 1536) v = g_ctx_b[b * HD + c - 1024];
    else if (c < 2048) v = g_ctx_p[b * HD + c - 1536];
    else if (c < 2080) v = db[b * PTRD + (c - 2048)];
    else               v = 0.f;
    g_xb[idx] = __float2bfloat16(v);
}

// =====================================================================
// GRU gate combine (sums split-K gi halves); writes hnew f32 + bf16.
// =====================================================================
__global__ void gru_gate_kernel(const float* __restrict__ h0)
{
    int idx = blockIdx.x * blockDim.x + threadIdx.x;
    if (idx >= BB * HD) return;
    int b = idx / HD, i = idx % HD;
    const float* gi = g_gi + (size_t)b * G3;
    const float* gi2 = g_gi2 + (size_t)b * G3;
    const float* gh = g_gh + (size_t)b * G3;
    float gr_ = gi[i] + gi2[i] + gh[i];
    float gz = gi[512 + i] + gi2[512 + i] + gh[512 + i];
    float r = 1.f / (1.f + expf(-gr_));
    float z = 1.f / (1.f + expf(-gz));
    float n = tanhf(gi[1024 + i] + gi2[1024 + i] + r * gh[1024 + i]);
    float hv = (1.f - z) * n + z * h0[idx];
    g_hnew[idx] = hv;
    g_hnb[idx] = __float2bfloat16(hv);
}

// =====================================================================
// Final: scatter cps, log-softmax over [gen | cps], merge + OOV.
// =====================================================================
__global__ __launch_bounds__(256) void final_kernel(
    const int* __restrict__ bspn_ids, const int* __restrict__ nounk,
    float* __restrict__ out)
{
    int b = blockIdx.x;
    int tid = threadIdx.x;
    __shared__ float s_cps[VD + TB];
    __shared__ float s_cpm[TB];
    __shared__ int   s_nk[TB];
    __shared__ float rbuf[256];

    for (int i = tid; i < VD + TB; i += 256) s_cps[i] = 0.f;
    if (tid < TB) {
        float c = g_cpraw[b * TB + tid];
        if (bspn_ids[b * TB + tid] == 0) c = NEGV;
        s_cpm[tid] = c;
        s_nk[tid] = nounk[b * TB + tid];
    }
    __syncthreads();
    if (tid == 0) {
        for (int j = 0; j < TB; j++) {
            int nk = s_nk[j];
            float c = s_cpm[j];
            if (nk < VD) s_cps[nk] += c;
            else         s_cps[VD + j] = c;
        }
    }
    __syncthreads();

    const float* genb = g_gen + (size_t)b * VD;
    float mx = -INFINITY;
    for (int i = tid; i < VD; i += 256) mx = fmaxf(mx, genb[i]);
    for (int i = tid; i < VD + TB; i += 256) mx = fmaxf(mx, s_cps[i]);
    rbuf[tid] = mx;
    __syncthreads();
    for (int s = 128; s > 0; s >>= 1) {
        if (tid < s) rbuf[tid] = fmaxf(rbuf[tid], rbuf[tid + s]);
        __syncthreads();
    }
    mx = rbuf[0];
    __syncthreads();
    float sm = 0.f;
    for (int i = tid; i < VD; i += 256) sm += expf(genb[i] - mx);
    for (int i = tid; i < VD + TB; i += 256) sm += expf(s_cps[i] - mx);
    rbuf[tid] = sm;
    __syncthreads();
    for (int s = 128; s > 0; s >>= 1) {
        if (tid < s) rbuf[tid] += rbuf[tid + s];
        __syncthreads();
    }
    float lse = mx + logf(rbuf[0]);
    __syncthreads();

    float* outb = out + (size_t)b * VOOVD;
    for (int n = tid; n < VD; n += 256) {
        float a = genb[n], c = s_cps[n];
        float m2 = fmaxf(a, c);
        outb[n] = m2 + logf(expf(a - m2) + expf(c - m2)) - lse;
    }
    for (int k = tid; k < VOOVD - VD; k += 256) {
        float add = 0.f;
        int target = VD + k;
        for (int j = 0; j < TB; j++)
            if (s_nk[j] == target) add += expf(s_cpm[j] - lse);
        outb[VD + k] = (add > 0.f) ? logf(add) : NEGV;
    }
}

// =====================================================================
// Host launcher
// =====================================================================
extern "C" void kernel_launch(void* const* d_in, const int* in_sizes, int n_in,
                              void* d_out, int out_size)
{
    const int*   dec_last_w = (const int*)  d_in[0];
    const float* h0         = (const float*)d_in[1];
    const float* usdx_h     = (const float*)d_in[2];
    const float* bspn_h     = (const float*)d_in[3];
    const float* pvaspn_h   = (const float*)d_in[4];
    const float* db         = (const float*)d_in[5];
    const int*   usdx_ids   = (const int*)  d_in[6];
    const int*   bspn_ids   = (const int*)  d_in[7];
    const int*   pvaspn_ids = (const int*)  d_in[8];
    const int*   bspn_nounk = (const int*)  d_in[9];
    const float* emb_table  = (const float*)d_in[11];
    const float* attn_W     = (const float*)d_in[12];
    const float* attn_b     = (const float*)d_in[13];
    const float* v_w        = (const float*)d_in[14];
    const float* Wcopy_w    = (const float*)d_in[15];
    const float* Wcopy_b    = (const float*)d_in[16];
    const float* Wgen_w     = (const float*)d_in[17];
    const float* Wgen_b     = (const float*)d_in[18];
    const float* gru_W_ih   = (const float*)d_in[19];
    const float* gru_W_hh   = (const float*)d_in[20];
    const float* gru_b_ih   = (const float*)d_in[21];
    const float* gru_b_hh   = (const float*)d_in[22];
    float* out = (float*)d_out;

    cudaFuncSetAttribute(score_attn_kernel,
                         cudaFuncAttributeMaxDynamicSharedMemorySize, SMEM_SZ);
    cudaFuncSetAttribute(tail_kernel,
                         cudaFuncAttributeMaxDynamicSharedMemorySize, SMEM_SZ);
    cudaFuncSetAttribute(mma_p_kernel,
                         cudaFuncAttributeMaxDynamicSharedMemorySize, GM_SMEM);
    cudaFuncSetAttribute(mma_gru_kernel,
                         cudaFuncAttributeMaxDynamicSharedMemorySize, GM_SMEM);

    // 0) stage all operands to bf16
    stage_all_kernel<<<(SO7 + 255) / 256, 256>>>(
        attn_W, Wcopy_w, gru_W_ih, gru_W_hh, Wgen_w, h0);

    // 1) p = h0 @ W1^T + attn_b  (bf16 mma)
    mma_p_kernel<<<4, 256, GM_SMEM>>>(attn_b);

    // 2) all three attention scores, one bf16 tensor-core launch
    score_attn_kernel<<<448, 256, SMEM_SZ>>>(usdx_h, bspn_h, pvaspn_h, v_w);

    // 3) softmax+context fused
    ctx_kernel<<<1536, 128>>>(usdx_h, bspn_h, pvaspn_h,
                              usdx_ids, bspn_ids, pvaspn_ids);

    // 4) GRU (split-K gi)
    assemble_x_kernel<<<(BB * XDP + 255) / 256, 256>>>(dec_last_w, emb_table, db);
    mma_gru_kernel<<<36, 256, GM_SMEM>>>(gru_b_ih, gru_b_hh);
    gru_gate_kernel<<<(BB * HD + 255) / 256, 256>>>(h0);

    // 5) cp scores + gen logits fused (both depend only on hnew)
    tail_kernel<<<152, 256, SMEM_SZ>>>(Wgen_b, Wcopy_b, bspn_h);

    // 6) final scatter + log-softmax + merge
    final_kernel<<<BB, 256>>>(bspn_ids, bspn_nounk, out);
}